// round 1
// baseline (speedup 1.0000x reference)
#include <cuda_runtime.h>
#include <cuda_fp16.h>
#include <cstdint>

#define DB 4
#define DT 256
#define DU 64
#define DENC 512
#define DPRED 640
#define DJ 640
#define DV 1024
#define BT (DB*DT)        // 1024 enc rows
#define BUROWS (DB*DU)    // 256 pred rows
#define M_TOTAL (BT*DU)   // 65536 joint rows

// ---------------- device scratch (no allocations allowed) ----------------
__device__ float  g_encP[BT * DJ];                 // 2.6 MB
__device__ float  g_predP[BUROWS * DJ];            // 0.66 MB
__device__ __half g_joint[65536 * 640];            // 84 MB, fp16 joint = tanh(enc+pred)
__device__ __half g_Wh[DV * DJ];                   // W_out transposed [v][k], fp16

// ---------------- FFMA-only tanh (XLA/Eigen rational, no MUFU) -----------
__device__ __forceinline__ float fast_tanh(float x) {
    const float CL = 7.90531110763549805f;
    float xc = fminf(fmaxf(x, -CL), CL);
    float x2 = xc * xc;
    float np = fmaf(x2, -2.76076847742355e-16f, 2.00018790482477e-13f);
    np = fmaf(x2, np, -8.60467152213735e-11f);
    np = fmaf(x2, np,  5.12229709037114e-08f);
    np = fmaf(x2, np,  1.48572235717979e-05f);
    np = fmaf(x2, np,  6.37261928875436e-04f);
    np = fmaf(x2, np,  4.89352455891786e-03f);
    np = np * xc;
    float dp = fmaf(x2, 1.19825839466702e-06f, 1.18534705686654e-04f);
    dp = fmaf(x2, dp, 2.26843463243900e-03f);
    dp = fmaf(x2, dp, 4.89352518554385e-03f);
    // reciprocal via bit-trick + 3 Newton steps (stays on fma/alu pipes)
    float r = __uint_as_float(0x7EF311C4u - __float_as_uint(dp));
    r = r * fmaf(-dp, r, 2.0f);
    r = r * fmaf(-dp, r, 2.0f);
    r = r * fmaf(-dp, r, 2.0f);
    return np * r;
}

// ---------------- small projection GEMMs (fp32, exact) -------------------
// out[r][j] = sum_k X[r][k] * W[k][j] + b[j];  16 rows per block, 640 threads.
template<int K, bool PRED>
__global__ void __launch_bounds__(640) proj_kernel(const float* __restrict__ X,
                                                   const float* __restrict__ W,
                                                   const float* __restrict__ bias) {
    float* out = PRED ? g_predP : g_encP;
    constexpr int ROWS = 16;
    __shared__ float sx[ROWS * K];
    const int j  = threadIdx.x;          // output column 0..639
    const int r0 = blockIdx.x * ROWS;
    for (int idx = j; idx < ROWS * K; idx += 640)
        sx[idx] = X[r0 * K + idx];       // rows contiguous -> flat coalesced copy
    __syncthreads();
    float acc[ROWS];
    float bj = bias[j];
#pragma unroll
    for (int r = 0; r < ROWS; r++) acc[r] = bj;
    for (int k = 0; k < K; k++) {
        float w = W[k * DJ + j];
#pragma unroll
        for (int r = 0; r < ROWS; r++) acc[r] = fmaf(sx[r * K + k], w, acc[r]);
    }
#pragma unroll
    for (int r = 0; r < ROWS; r++) out[(r0 + r) * DJ + j] = acc[r];
}

// ---------------- joint = tanh(encP + predP) -> fp16, computed ONCE ------
__global__ void __launch_bounds__(256) joint_tanh_kernel() {
    int idx = blockIdx.x * 256 + threadIdx.x;    // 65536*80 chunks of 8
    int m  = idx / 80;
    int kq = (idx - m * 80) * 8;
    int bt = m >> 6;                             // m = bt*64 + u
    int u  = m & 63;
    int b  = bt >> 8;                            // bt / 256
    const float4* e = (const float4*)(g_encP  + (size_t)bt * DJ + kq);
    const float4* p = (const float4*)(g_predP + (size_t)(b * DU + u) * DJ + kq);
    float4 e0 = e[0], e1 = e[1];
    float4 p0 = p[0], p1 = p[1];
    __half2 q0 = __floats2half2_rn(fast_tanh(e0.x + p0.x), fast_tanh(e0.y + p0.y));
    __half2 q1 = __floats2half2_rn(fast_tanh(e0.z + p0.z), fast_tanh(e0.w + p0.w));
    __half2 q2 = __floats2half2_rn(fast_tanh(e1.x + p1.x), fast_tanh(e1.y + p1.y));
    __half2 q3 = __floats2half2_rn(fast_tanh(e1.z + p1.z), fast_tanh(e1.w + p1.w));
    int4 v;
    v.x = *(int*)&q0; v.y = *(int*)&q1; v.z = *(int*)&q2; v.w = *(int*)&q3;
    *(int4*)(g_joint + (size_t)m * DJ + kq) = v;
}

// ---------------- W_out -> fp16 transposed [v][k] -------------------------
__global__ void __launch_bounds__(256) wconv_kernel(const float* __restrict__ W) {
    int idx = blockIdx.x * 256 + threadIdx.x;    // 640*1024 elements
    int k = idx >> 10;
    int v = idx & 1023;
    g_Wh[v * DJ + k] = __float2half_rn(W[idx]);
}

// ---------------- main GEMM: (65536x640) x (640x1024), fp16 mma, fp32 acc -
__device__ __forceinline__ void mma16816(float c[4], const uint32_t a[4], const uint32_t b[2]) {
    asm volatile(
        "mma.sync.aligned.m16n8k16.row.col.f32.f16.f16.f32 "
        "{%0,%1,%2,%3}, {%4,%5,%6,%7}, {%8,%9}, {%0,%1,%2,%3};\n"
        : "+f"(c[0]), "+f"(c[1]), "+f"(c[2]), "+f"(c[3])
        : "r"(a[0]), "r"(a[1]), "r"(a[2]), "r"(a[3]), "r"(b[0]), "r"(b[1]));
}

#define KS 24   // padded smem row stride in halves (48B) -> conflict-free frag LDS

__global__ void __launch_bounds__(256, 2) gemm_kernel(const float* __restrict__ b_out,
                                                      float* __restrict__ out) {
    __shared__ __half As[128 * KS];   // A tile [m][k], k contiguous
    __shared__ __half Bs[128 * KS];   // B tile [n][k], k contiguous (W_out^T)
    const int tid  = threadIdx.x;
    const int warp = tid >> 5;
    const int lane = tid & 31;
    const int g = lane >> 2;          // groupID
    const int t = lane & 3;           // thread-in-group
    const int wm = (warp >> 2) * 64;  // warp tile 64x32
    const int wn = (warp & 3) * 32;
    const int m0 = blockIdx.y * 128;
    const int n0 = blockIdx.x * 128;

    // gmem->smem copy mapping: 256 threads, 1 int4 (8 halves) each per tile
    const int crow = tid >> 1;
    const int ch8  = (tid & 1) * 8;
    const __half* aSrc = g_joint + (size_t)(m0 + crow) * DJ + ch8;
    const __half* bSrc = g_Wh    + (size_t)(n0 + crow) * DJ + ch8;
    __half* aDst = As + crow * KS + ch8;
    __half* bDst = Bs + crow * KS + ch8;

    float acc[4][4][4];
#pragma unroll
    for (int i = 0; i < 4; i++)
#pragma unroll
        for (int j = 0; j < 4; j++)
#pragma unroll
            for (int q = 0; q < 4; q++) acc[i][j][q] = 0.0f;

    int4 pa = *(const int4*)aSrc;
    int4 pb = *(const int4*)bSrc;

    for (int kt = 0; kt < 40; ++kt) {          // K = 640, BK = 16
        *(int4*)aDst = pa;
        *(int4*)bDst = pb;
        __syncthreads();
        if (kt < 39) {                          // register prefetch of next tile
            pa = *(const int4*)(aSrc + (kt + 1) * 16);
            pb = *(const int4*)(bSrc + (kt + 1) * 16);
        }
        uint32_t af[4][4], bf[4][2];
#pragma unroll
        for (int i = 0; i < 4; i++) {
            const __half* ab = As + (wm + i * 16 + g) * KS + 2 * t;
            af[i][0] = *(const uint32_t*)(ab);
            af[i][1] = *(const uint32_t*)(ab + 8 * KS);
            af[i][2] = *(const uint32_t*)(ab + 8);
            af[i][3] = *(const uint32_t*)(ab + 8 * KS + 8);
        }
#pragma unroll
        for (int j = 0; j < 4; j++) {
            const __half* bb = Bs + (wn + j * 8 + g) * KS + 2 * t;
            bf[j][0] = *(const uint32_t*)(bb);
            bf[j][1] = *(const uint32_t*)(bb + 8);
        }
#pragma unroll
        for (int i = 0; i < 4; i++)
#pragma unroll
            for (int j = 0; j < 4; j++)
                mma16816(acc[i][j], af[i], bf[j]);
        __syncthreads();
    }

    // epilogue: + bias, clamp to +-15, vectorized float2 stores
#pragma unroll
    for (int j = 0; j < 4; j++) {
        int col = n0 + wn + j * 8 + 2 * t;
        float bo0 = b_out[col], bo1 = b_out[col + 1];
#pragma unroll
        for (int i = 0; i < 4; i++) {
            int r0 = m0 + wm + i * 16 + g;
            float2 v0, v1;
            v0.x = fminf(fmaxf(acc[i][j][0] + bo0, -15.0f), 15.0f);
            v0.y = fminf(fmaxf(acc[i][j][1] + bo1, -15.0f), 15.0f);
            v1.x = fminf(fmaxf(acc[i][j][2] + bo0, -15.0f), 15.0f);
            v1.y = fminf(fmaxf(acc[i][j][3] + bo1, -15.0f), 15.0f);
            *(float2*)(out + (size_t)r0 * DV + col)       = v0;
            *(float2*)(out + (size_t)(r0 + 8) * DV + col) = v1;
        }
    }
}

// ---------------- launch ---------------------------------------------------
extern "C" void kernel_launch(void* const* d_in, const int* in_sizes, int n_in,
                              void* d_out, int out_size) {
    const float* enc    = (const float*)d_in[0];
    const float* pred   = (const float*)d_in[1];
    const float* W_enc  = (const float*)d_in[2];
    const float* b_enc  = (const float*)d_in[3];
    const float* W_pred = (const float*)d_in[4];
    const float* b_pred = (const float*)d_in[5];
    const float* W_out  = (const float*)d_in[6];
    const float* b_out  = (const float*)d_in[7];
    float* out = (float*)d_out;

    proj_kernel<DENC,  false><<<BT / 16,     640>>>(enc,  W_enc,  b_enc);
    proj_kernel<DPRED, true ><<<BUROWS / 16, 640>>>(pred, W_pred, b_pred);
    wconv_kernel<<<(DV * DJ) / 256, 256>>>(W_out);
    joint_tanh_kernel<<<(M_TOTAL * 80) / 256, 256>>>();
    gemm_kernel<<<dim3(DV / 128, M_TOTAL / 128), 256>>>(b_out, out);
}

// round 3
// speedup vs baseline: 1.3803x; 1.3803x over previous
#include <cuda_runtime.h>
#include <cuda_fp16.h>
#include <cstdint>

#define DB 4
#define DT 256
#define DU 64
#define DENC 512
#define DPRED 640
#define DJ 640
#define DV 1024
#define BT (DB*DT)        // 1024 enc rows
#define BUROWS (DB*DU)    // 256 pred rows
#define M_TOTAL (BT*DU)   // 65536 joint rows

// ---------------- device scratch (no allocations allowed) ----------------
__device__ float  g_encP[BT * DJ];                 // 2.6 MB
__device__ float  g_predP[BUROWS * DJ];            // 0.66 MB
__device__ __half g_joint[(size_t)M_TOTAL * DJ];   // 84 MB, fp16 joint = tanh(enc+pred)
__device__ __half g_Wh[DV * DJ];                   // W_out transposed [v][k], fp16

// ---------------- FFMA-only tanh (XLA/Eigen rational, no MUFU) -----------
__device__ __forceinline__ float fast_tanh(float x) {
    const float CL = 7.90531110763549805f;
    float xc = fminf(fmaxf(x, -CL), CL);
    float x2 = xc * xc;
    float np = fmaf(x2, -2.76076847742355e-16f, 2.00018790482477e-13f);
    np = fmaf(x2, np, -8.60467152213735e-11f);
    np = fmaf(x2, np,  5.12229709037114e-08f);
    np = fmaf(x2, np,  1.48572235717979e-05f);
    np = fmaf(x2, np,  6.37261928875436e-04f);
    np = fmaf(x2, np,  4.89352455891786e-03f);
    np = np * xc;
    float dp = fmaf(x2, 1.19825839466702e-06f, 1.18534705686654e-04f);
    dp = fmaf(x2, dp, 2.26843463243900e-03f);
    dp = fmaf(x2, dp, 4.89352518554385e-03f);
    float r = __uint_as_float(0x7EF311C4u - __float_as_uint(dp));
    r = r * fmaf(-dp, r, 2.0f);
    r = r * fmaf(-dp, r, 2.0f);
    r = r * fmaf(-dp, r, 2.0f);
    return np * r;
}

// ---------------- small projection GEMMs (fp32, exact) -------------------
template<int K, bool PRED>
__global__ void __launch_bounds__(640) proj_kernel(const float* __restrict__ X,
                                                   const float* __restrict__ W,
                                                   const float* __restrict__ bias) {
    float* out = PRED ? g_predP : g_encP;
    constexpr int ROWS = 16;
    __shared__ float sx[ROWS * K];
    const int j  = threadIdx.x;
    const int r0 = blockIdx.x * ROWS;
    for (int idx = j; idx < ROWS * K; idx += 640)
        sx[idx] = X[r0 * K + idx];
    __syncthreads();
    float acc[ROWS];
    float bj = bias[j];
#pragma unroll
    for (int r = 0; r < ROWS; r++) acc[r] = bj;
    for (int k = 0; k < K; k++) {
        float w = W[k * DJ + j];
#pragma unroll
        for (int r = 0; r < ROWS; r++) acc[r] = fmaf(sx[r * K + k], w, acc[r]);
    }
#pragma unroll
    for (int r = 0; r < ROWS; r++) out[(r0 + r) * DJ + j] = acc[r];
}

// ---------------- joint = tanh(encP + predP) -> fp16, computed ONCE ------
__global__ void __launch_bounds__(256) joint_tanh_kernel() {
    int idx = blockIdx.x * 256 + threadIdx.x;
    int m  = idx / 80;
    int kq = (idx - m * 80) * 8;
    int bt = m >> 6;
    int u  = m & 63;
    int b  = bt >> 8;
    const float4* e = (const float4*)(g_encP  + (size_t)bt * DJ + kq);
    const float4* p = (const float4*)(g_predP + (size_t)(b * DU + u) * DJ + kq);
    float4 e0 = e[0], e1 = e[1];
    float4 p0 = p[0], p1 = p[1];
    __half2 q0 = __floats2half2_rn(fast_tanh(e0.x + p0.x), fast_tanh(e0.y + p0.y));
    __half2 q1 = __floats2half2_rn(fast_tanh(e0.z + p0.z), fast_tanh(e0.w + p0.w));
    __half2 q2 = __floats2half2_rn(fast_tanh(e1.x + p1.x), fast_tanh(e1.y + p1.y));
    __half2 q3 = __floats2half2_rn(fast_tanh(e1.z + p1.z), fast_tanh(e1.w + p1.w));
    int4 v;
    v.x = *(int*)&q0; v.y = *(int*)&q1; v.z = *(int*)&q2; v.w = *(int*)&q3;
    *(int4*)(g_joint + (size_t)m * DJ + kq) = v;
}

// ---------------- W_out -> fp16 transposed [v][k] -------------------------
__global__ void __launch_bounds__(256) wconv_kernel(const float* __restrict__ W) {
    int idx = blockIdx.x * 256 + threadIdx.x;
    int k = idx >> 10;
    int v = idx & 1023;
    g_Wh[v * DJ + k] = __float2half_rn(W[idx]);
}

// ==================== GEMM: ldmatrix + cp.async pipeline ==================
// D[65536,1024] = joint(f16) x W_out(f16), f32 accum via mma.sync.m16n8k16.
// CTA tile 128x128, warp tile 32x64 (8 warps), BK=64, 2-stage cp.async ring.

#define BM 128
#define BN 128
#define BK 64
#define KTILES 10          // 640 / 64
#define STG 32768          // bytes per stage: A 16KB + B 16KB
#define DYN_SMEM (2*STG)

__device__ __forceinline__ uint32_t smem_u32(const void* p) {
    uint32_t a;
    asm("{ .reg .u64 t; cvta.to.shared.u64 t, %1; cvt.u32.u64 %0, t; }" : "=r"(a) : "l"(p));
    return a;
}
__device__ __forceinline__ uint32_t swz(uint32_t o) { return o ^ ((o >> 3) & 0x70); }

__device__ __forceinline__ void cp16(uint32_t dst, const void* src) {
    asm volatile("cp.async.cg.shared.global [%0], [%1], 16;" :: "r"(dst), "l"(src));
}
__device__ __forceinline__ void ldsm4(uint32_t& r0, uint32_t& r1, uint32_t& r2,
                                      uint32_t& r3, uint32_t a) {
    asm volatile("ldmatrix.sync.aligned.m8n8.x4.shared.b16 {%0,%1,%2,%3}, [%4];"
                 : "=r"(r0), "=r"(r1), "=r"(r2), "=r"(r3) : "r"(a));
}
__device__ __forceinline__ void mma16816(float c[4], const uint32_t a[4], const uint32_t b[2]) {
    asm volatile(
        "mma.sync.aligned.m16n8k16.row.col.f32.f16.f16.f32 "
        "{%0,%1,%2,%3}, {%4,%5,%6,%7}, {%8,%9}, {%0,%1,%2,%3};\n"
        : "+f"(c[0]), "+f"(c[1]), "+f"(c[2]), "+f"(c[3])
        : "r"(a[0]), "r"(a[1]), "r"(a[2]), "r"(a[3]), "r"(b[0]), "r"(b[1]));
}

__global__ void __launch_bounds__(256, 2) gemm_lm(const float* __restrict__ b_out,
                                                  float* __restrict__ out) {
    extern __shared__ char ds[];
    const uint32_t sbase = smem_u32(ds);
    const int tid  = threadIdx.x;
    const int warp = tid >> 5;
    const int lane = tid & 31;
    const int g = lane >> 2;
    const int t = lane & 3;
    const int wm = (warp >> 1) * 32;
    const int wn = (warp & 1) * 64;
    const int m0 = blockIdx.y * BM;
    const int n0 = blockIdx.x * BN;

    const __half* aG = g_joint + (size_t)m0 * DJ;
    const __half* bG = g_Wh    + (size_t)n0 * DJ;

    // ---- stage loader: 256 threads x 8 cp.async(16B) = 32KB ----
    auto load_stage = [&](int s, int kt) {
        const uint32_t stA = sbase + s * STG;
        const uint32_t stB = stA + 16384;
        const int koff = kt * BK;
#pragma unroll
        for (int q = 0; q < 4; q++) {
            int id = tid + 256 * q;
            int row = id >> 3, c = id & 7;
            cp16(stA + swz(row * 128 + c * 16), aG + (size_t)row * DJ + koff + c * 8);
        }
#pragma unroll
        for (int q = 0; q < 4; q++) {
            int id = tid + 256 * q;
            int row = id >> 3, c = id & 7;
            cp16(stB + swz(row * 128 + c * 16), bG + (size_t)row * DJ + koff + c * 8);
        }
        asm volatile("cp.async.commit_group;" ::: "memory");
    };

    // ---- per-lane ldmatrix addressing (swizzle XOR constant per lane) ----
    const int rowA  = wm + (lane & 15);              // + i*16
    const uint32_t kbA  = (lane >> 4) * 16;          // 16B chunk within k16 pair
    const uint32_t xorA = (uint32_t)(rowA & 7) * 16;
    const int rowB  = wn + (lane & 7) + ((lane >> 4) << 3);  // + jp*16
    const uint32_t kbB  = ((lane >> 3) & 1) * 16;
    const uint32_t xorB = (uint32_t)(lane & 7) * 16;

    float acc[2][8][4];
#pragma unroll
    for (int i = 0; i < 2; i++)
#pragma unroll
        for (int j = 0; j < 8; j++)
#pragma unroll
            for (int q = 0; q < 4; q++) acc[i][j][q] = 0.0f;

    auto compute = [&](int s) {
        const uint32_t stA = sbase + s * STG;
        const uint32_t stB = stA + 16384;
#pragma unroll
        for (int ks = 0; ks < 4; ks++) {
            const uint32_t kb = ks * 32;             // 32B per k16 step
            uint32_t a[2][4];
#pragma unroll
            for (int i = 0; i < 2; i++)
                ldsm4(a[i][0], a[i][1], a[i][2], a[i][3],
                      stA + (uint32_t)(rowA + i * 16) * 128 + ((kb + kbA) ^ xorA));
            uint32_t b[8][2];
#pragma unroll
            for (int jp = 0; jp < 4; jp++) {
                uint32_t r0, r1, r2, r3;
                ldsm4(r0, r1, r2, r3,
                      stB + (uint32_t)(rowB + jp * 16) * 128 + ((kb + kbB) ^ xorB));
                b[2*jp][0] = r0; b[2*jp][1] = r1;
                b[2*jp+1][0] = r2; b[2*jp+1][1] = r3;
            }
#pragma unroll
            for (int i = 0; i < 2; i++)
#pragma unroll
                for (int j = 0; j < 8; j++)
                    mma16816(acc[i][j], a[i], b[j]);
        }
    };

    // ---- pipelined main loop ----
    load_stage(0, 0);
    load_stage(1, 1);
#pragma unroll 1
    for (int kt = 0; kt < KTILES; kt++) {
        asm volatile("cp.async.wait_group 1;" ::: "memory");
        __syncthreads();
        compute(kt & 1);
        __syncthreads();
        if (kt + 2 < KTILES) load_stage(kt & 1, kt + 2);
        else asm volatile("cp.async.commit_group;" ::: "memory");
    }

    // ---- epilogue: + bias, clamp, vectorized float2 stores ----
#pragma unroll
    for (int j = 0; j < 8; j++) {
        int col = n0 + wn + j * 8 + 2 * t;
        float bo0 = __ldg(b_out + col), bo1 = __ldg(b_out + col + 1);
#pragma unroll
        for (int i = 0; i < 2; i++) {
            int r0 = m0 + wm + i * 16 + g;
            float2 v0, v1;
            v0.x = fminf(fmaxf(acc[i][j][0] + bo0, -15.0f), 15.0f);
            v0.y = fminf(fmaxf(acc[i][j][1] + bo1, -15.0f), 15.0f);
            v1.x = fminf(fmaxf(acc[i][j][2] + bo0, -15.0f), 15.0f);
            v1.y = fminf(fmaxf(acc[i][j][3] + bo1, -15.0f), 15.0f);
            *(float2*)(out + (size_t)r0 * DV + col)       = v0;
            *(float2*)(out + (size_t)(r0 + 8) * DV + col) = v1;
        }
    }
}

// ---------------- launch ---------------------------------------------------
extern "C" void kernel_launch(void* const* d_in, const int* in_sizes, int n_in,
                              void* d_out, int out_size) {
    const float* enc    = (const float*)d_in[0];
    const float* pred   = (const float*)d_in[1];
    const float* W_enc  = (const float*)d_in[2];
    const float* b_enc  = (const float*)d_in[3];
    const float* W_pred = (const float*)d_in[4];
    const float* b_pred = (const float*)d_in[5];
    const float* W_out  = (const float*)d_in[6];
    const float* b_out  = (const float*)d_in[7];
    float* out = (float*)d_out;

    cudaFuncSetAttribute(gemm_lm, cudaFuncAttributeMaxDynamicSharedMemorySize, DYN_SMEM);

    proj_kernel<DENC,  false><<<BT / 16,     640>>>(enc,  W_enc,  b_enc);
    proj_kernel<DPRED, true ><<<BUROWS / 16, 640>>>(pred, W_pred, b_pred);
    wconv_kernel<<<(DV * DJ) / 256, 256>>>(W_out);
    joint_tanh_kernel<<<(M_TOTAL * 80) / 256, 256>>>();
    gemm_lm<<<dim3(DV / BN, M_TOTAL / BM), 256, DYN_SMEM>>>(b_out, out);
}